// round 4
// baseline (speedup 1.0000x reference)
#include <cuda_runtime.h>
#include <math.h>

// Problem constants
constexpr int Bc = 2, Tc = 2048, Cc = 1024, Hc = 16, Dc = 64;
constexpr int Mc = Bc * Tc;  // 4096 rows

// Scratch (static device globals — no allocation)
__device__ float g_q[Mc * Cc];    // [B,H,T,D]
__device__ float g_k[Mc * Cc];    // [B,H,T,D]
__device__ float g_v[Mc * Cc];    // [B,H,T,D]
__device__ float g_att[Mc * Cc];  // [B,T,C]

// ---------------------------------------------------------------------------
// Tiled fp32 GEMM:  out[m,n] = sum_k A[m,k] * W[n,k] + bias[n]   (A: MxK, W: NxK)
// BM=BN=128, BK=8, 256 threads, 8x8 per-thread tile.
// SPLIT_HEADS: write to [B,H,T,D] layout instead of [M,N].
// ---------------------------------------------------------------------------
template<bool SPLIT_HEADS>
__device__ __forceinline__ void gemm_nt_body(
    const float* __restrict__ A, const float* __restrict__ W,
    const float* __restrict__ bias, float* __restrict__ out)
{
    __shared__ float As[8][128];
    __shared__ float Bs[8][128];
    const int tid = threadIdx.x;
    const int tr = tid >> 4;        // 0..15 (row group)
    const int tc = tid & 15;        // 0..15 (col group)
    const int m0 = blockIdx.y * 128;
    const int n0 = blockIdx.x * 128;
    const int lrow = tid >> 1;      // 0..127
    const int lcol = (tid & 1) << 2;// 0 or 4

    const float* Arow = A + (size_t)(m0 + lrow) * Cc + lcol;
    const float* Wrow = W + (size_t)(n0 + lrow) * Cc + lcol;

    float acc[8][8];
    #pragma unroll
    for (int i = 0; i < 8; i++)
        #pragma unroll
        for (int j = 0; j < 8; j++) acc[i][j] = 0.f;

    for (int k0 = 0; k0 < Cc; k0 += 8) {
        float4 a4 = *(const float4*)(Arow + k0);
        float4 b4 = *(const float4*)(Wrow + k0);
        __syncthreads();
        As[lcol + 0][lrow] = a4.x; As[lcol + 1][lrow] = a4.y;
        As[lcol + 2][lrow] = a4.z; As[lcol + 3][lrow] = a4.w;
        Bs[lcol + 0][lrow] = b4.x; Bs[lcol + 1][lrow] = b4.y;
        Bs[lcol + 2][lrow] = b4.z; Bs[lcol + 3][lrow] = b4.w;
        __syncthreads();
        #pragma unroll
        for (int kk = 0; kk < 8; kk++) {
            float a[8], b[8];
            *(float4*)(a)     = *(const float4*)&As[kk][tr * 8];
            *(float4*)(a + 4) = *(const float4*)&As[kk][tr * 8 + 4];
            *(float4*)(b)     = *(const float4*)&Bs[kk][tc * 8];
            *(float4*)(b + 4) = *(const float4*)&Bs[kk][tc * 8 + 4];
            #pragma unroll
            for (int i = 0; i < 8; i++)
                #pragma unroll
                for (int j = 0; j < 8; j++)
                    acc[i][j] = fmaf(a[i], b[j], acc[i][j]);
        }
    }

    #pragma unroll
    for (int i = 0; i < 8; i++) {
        const int m = m0 + tr * 8 + i;
        const int bb = m >> 11;          // / T
        const int t  = m & (Tc - 1);
        #pragma unroll
        for (int j = 0; j < 8; j++) {
            const int n = n0 + tc * 8 + j;
            const float v = acc[i][j] + bias[n];
            if (SPLIT_HEADS) {
                const int h = n >> 6;     // / D
                const int d = n & 63;
                out[((size_t)(bb * Hc + h) * Tc + t) * Dc + d] = v;
            } else {
                out[(size_t)m * Cc + n] = v;
            }
        }
    }
}

__global__ __launch_bounds__(256) void qkv_kernel(
    const float* __restrict__ x,
    const float* __restrict__ Wq, const float* __restrict__ bq,
    const float* __restrict__ Wk, const float* __restrict__ bk,
    const float* __restrict__ Wv, const float* __restrict__ bv)
{
    const float* W; const float* bias; float* out;
    switch (blockIdx.z) {
        case 0:  W = Wq; bias = bq; out = g_q; break;
        case 1:  W = Wk; bias = bk; out = g_k; break;
        default: W = Wv; bias = bv; out = g_v; break;
    }
    gemm_nt_body<true>(x, W, bias, out);
}

__global__ __launch_bounds__(256) void proj_kernel(
    const float* __restrict__ Wp, const float* __restrict__ bp,
    float* __restrict__ out)
{
    gemm_nt_body<false>(g_att, Wp, bp, out);
}

// ---------------------------------------------------------------------------
// Causal flash attention, fp32 SIMT.
// Block = 64 q-rows of one (b,h); thread i owns q-row i (q + o in registers).
// Iterate KV tiles of 64 with online softmax (chunked by 8 columns).
// ---------------------------------------------------------------------------
__global__ __launch_bounds__(64) void flash_kernel()
{
    __shared__ float Ks[64][64];
    __shared__ float Vs[64][64];
    const int tid = threadIdx.x;
    const int qt = blockIdx.x, h = blockIdx.y, b = blockIdx.z;
    const size_t head_off = (size_t)(b * Hc + h) * Tc * Dc;
    const float* qb = g_q + head_off;
    const float* kb = g_k + head_off;
    const float* vb = g_v + head_off;
    const int qglob = qt * 64 + tid;
    const float NEG_INF = __int_as_float(0xff800000);

    // q row -> registers, pre-scaled by 1/sqrt(D)
    float qr[64];
    {
        const float4* qsrc = (const float4*)(qb + (size_t)qglob * Dc);
        #pragma unroll
        for (int k4 = 0; k4 < 16; k4++) {
            float4 t4 = qsrc[k4];
            qr[k4 * 4 + 0] = t4.x * 0.125f;
            qr[k4 * 4 + 1] = t4.y * 0.125f;
            qr[k4 * 4 + 2] = t4.z * 0.125f;
            qr[k4 * 4 + 3] = t4.w * 0.125f;
        }
    }

    float o[64];
    #pragma unroll
    for (int d = 0; d < 64; d++) o[d] = 0.f;
    float mi = NEG_INF, li = 0.f;

    #pragma unroll 1
    for (int kt = 0; kt <= qt; kt++) {
        __syncthreads();
        {   // cooperative coalesced tile copy (tiles are contiguous in [T,D])
            const float4* ksrc = (const float4*)(kb + (size_t)kt * 64 * Dc);
            const float4* vsrc = (const float4*)(vb + (size_t)kt * 64 * Dc);
            float4* kd = (float4*)&Ks[0][0];
            float4* vd = (float4*)&Vs[0][0];
            for (int idx = tid; idx < 1024; idx += 64) {
                kd[idx] = ksrc[idx];
                vd[idx] = vsrc[idx];
            }
        }
        __syncthreads();
        const bool diag = (kt == qt);

        #pragma unroll 1
        for (int j0 = 0; j0 < 64; j0 += 8) {
            if (diag && j0 > tid) break;   // fully-masked chunk; later ones too

            float s[8];
            #pragma unroll
            for (int jj = 0; jj < 8; jj++) {
                const float4* krow = (const float4*)&Ks[j0 + jj][0];
                float a0 = 0.f, a1 = 0.f, a2 = 0.f, a3 = 0.f;
                #pragma unroll
                for (int k4 = 0; k4 < 16; k4++) {
                    float4 kv = krow[k4];
                    a0 = fmaf(qr[k4 * 4 + 0], kv.x, a0);
                    a1 = fmaf(qr[k4 * 4 + 1], kv.y, a1);
                    a2 = fmaf(qr[k4 * 4 + 2], kv.z, a2);
                    a3 = fmaf(qr[k4 * 4 + 3], kv.w, a3);
                }
                float sv = (a0 + a1) + (a2 + a3);
                if (diag && (j0 + jj > tid)) sv = NEG_INF;
                s[jj] = sv;
            }

            float mc = s[0];
            #pragma unroll
            for (int jj = 1; jj < 8; jj++) mc = fmaxf(mc, s[jj]);
            const float mnew = fmaxf(mi, mc);
            const float corr = __expf(mi - mnew);
            li *= corr;
            #pragma unroll
            for (int d = 0; d < 64; d++) o[d] *= corr;

            float p[8];
            #pragma unroll
            for (int jj = 0; jj < 8; jj++) {
                p[jj] = __expf(s[jj] - mnew);
                li += p[jj];
            }
            mi = mnew;

            #pragma unroll
            for (int jj = 0; jj < 8; jj++) {
                const float4* vrow = (const float4*)&Vs[j0 + jj][0];
                #pragma unroll
                for (int k4 = 0; k4 < 16; k4++) {
                    float4 vv = vrow[k4];
                    o[k4 * 4 + 0] = fmaf(p[jj], vv.x, o[k4 * 4 + 0]);
                    o[k4 * 4 + 1] = fmaf(p[jj], vv.y, o[k4 * 4 + 1]);
                    o[k4 * 4 + 2] = fmaf(p[jj], vv.z, o[k4 * 4 + 2]);
                    o[k4 * 4 + 3] = fmaf(p[jj], vv.w, o[k4 * 4 + 3]);
                }
            }
        }
    }

    const float inv = 1.f / li;
    float* yrow = g_att + ((size_t)b * Tc + qglob) * Cc + h * Dc;
    #pragma unroll
    for (int k4 = 0; k4 < 16; k4++) {
        float4 w4;
        w4.x = o[k4 * 4 + 0] * inv;
        w4.y = o[k4 * 4 + 1] * inv;
        w4.z = o[k4 * 4 + 2] * inv;
        w4.w = o[k4 * 4 + 3] * inv;
        ((float4*)yrow)[k4] = w4;
    }
}

// ---------------------------------------------------------------------------
// Input order (setup_inputs): x, Wk, bk, Wq, bq, Wv, bv, Wp, bp
// ---------------------------------------------------------------------------
extern "C" void kernel_launch(void* const* d_in, const int* in_sizes, int n_in,
                              void* d_out, int out_size)
{
    const float* x  = (const float*)d_in[0];
    const float* Wk = (const float*)d_in[1];
    const float* bk = (const float*)d_in[2];
    const float* Wq = (const float*)d_in[3];
    const float* bq = (const float*)d_in[4];
    const float* Wv = (const float*)d_in[5];
    const float* bv = (const float*)d_in[6];
    const float* Wp = (const float*)d_in[7];
    const float* bp = (const float*)d_in[8];
    float* out = (float*)d_out;

    dim3 gq(Cc / 128, Mc / 128, 3);
    qkv_kernel<<<gq, 256>>>(x, Wq, bq, Wk, bk, Wv, bv);

    flash_kernel<<<dim3(Tc / 64, Hc, Bc), 64>>>();

    proj_kernel<<<dim3(Cc / 128, Mc / 128, 1), 256>>>(Wp, bp, out);
}

// round 16
// speedup vs baseline: 1.5979x; 1.5979x over previous
#include <cuda_runtime.h>
#include <cuda_bf16.h>
#include <math.h>
#include <stdint.h>

// Problem constants
constexpr int Bc = 2, Tc = 2048, Cc = 1024, Hc = 16, Dc = 64;
constexpr int Mc = Bc * Tc;  // 4096 rows

// ---------------------------------------------------------------------------
// Scratch (static device globals — no allocation)
// ---------------------------------------------------------------------------
__device__ float g_q[Mc * Cc];    // [B,H,T,D]
__device__ float g_k[Mc * Cc];    // [B,H,T,D]
__device__ float g_v[Mc * Cc];    // [B,H,T,D]
__device__ float g_att[Mc * Cc];  // [B,T,C]

__device__ __nv_bfloat16 g_xh[Mc * Cc], g_xl[Mc * Cc];
__device__ __nv_bfloat16 g_ah[Mc * Cc], g_al[Mc * Cc];
__device__ __nv_bfloat16 g_wqh[Cc * Cc], g_wql[Cc * Cc];
__device__ __nv_bfloat16 g_wkh[Cc * Cc], g_wkl[Cc * Cc];
__device__ __nv_bfloat16 g_wvh[Cc * Cc], g_wvl[Cc * Cc];
__device__ __nv_bfloat16 g_wph[Cc * Cc], g_wpl[Cc * Cc];

// ---------------------------------------------------------------------------
// Portable PTX helpers (base compute_103 ISA: mma.sync / ldmatrix / cp.async)
// ---------------------------------------------------------------------------
__device__ __forceinline__ uint32_t smem_u32_of(const void* p) {
    uint32_t a;
    asm("{ .reg .u64 t; cvta.to.shared.u64 t, %1; cvt.u32.u64 %0, t; }" : "=r"(a) : "l"(p));
    return a;
}

#define CP_ASYNC16(dst, src) \
    asm volatile("cp.async.cg.shared.global [%0], [%1], 16;" :: "r"(dst), "l"(src) : "memory")
#define CP_COMMIT() asm volatile("cp.async.commit_group;" ::: "memory")
#define CP_WAIT(n)  asm volatile("cp.async.wait_group %0;" :: "n"(n) : "memory")

#define LDM4(r, addr) \
    asm volatile("ldmatrix.sync.aligned.m8n8.x4.shared.b16 {%0,%1,%2,%3}, [%4];" \
        : "=r"((r)[0]), "=r"((r)[1]), "=r"((r)[2]), "=r"((r)[3]) : "r"(addr))

#define MMA_BF16(d, a, b0v, b1v) \
    asm volatile("mma.sync.aligned.m16n8k16.row.col.f32.bf16.bf16.f32 " \
        "{%0,%1,%2,%3}, {%4,%5,%6,%7}, {%8,%9}, {%0,%1,%2,%3};" \
        : "+f"((d)[0]), "+f"((d)[1]), "+f"((d)[2]), "+f"((d)[3]) \
        : "r"((a)[0]), "r"((a)[1]), "r"((a)[2]), "r"((a)[3]), "r"(b0v), "r"(b1v))

// ---------------------------------------------------------------------------
// fp32 -> (hi, lo) bf16 split: x = hi + lo + O(2^-16 * x)
// ---------------------------------------------------------------------------
__global__ __launch_bounds__(256) void convert_kernel(
    const float* __restrict__ src, __nv_bfloat16* __restrict__ hi,
    __nv_bfloat16* __restrict__ lo, int n4)
{
    int i = blockIdx.x * blockDim.x + threadIdx.x;
    if (i >= n4) return;
    float4 x = ((const float4*)src)[i];
    float xs[4] = {x.x, x.y, x.z, x.w};
    uint16_t h[4], l[4];
#pragma unroll
    for (int j = 0; j < 4; j++) {
        __nv_bfloat16 hb = __float2bfloat16(xs[j]);
        __nv_bfloat16 lb = __float2bfloat16(xs[j] - __bfloat162float(hb));
        h[j] = __bfloat16_as_ushort(hb);
        l[j] = __bfloat16_as_ushort(lb);
    }
    uint2 ph, pl;
    ph.x = ((uint32_t)h[1] << 16) | h[0];
    ph.y = ((uint32_t)h[3] << 16) | h[2];
    pl.x = ((uint32_t)l[1] << 16) | l[0];
    pl.y = ((uint32_t)l[3] << 16) | l[2];
    ((uint2*)hi)[i] = ph;
    ((uint2*)lo)[i] = pl;
}

// ---------------------------------------------------------------------------
// Warp-MMA bf16x3 GEMM:  out[m,n] = sum_k A[m,k]*W[n,k] + bias[n]
// CTA 128x128, 8 warps (2x4), warp tile 64x32. K chunks of 32, cp.async
// double-buffered. Smem row stride 80B -> conflict-free ldmatrix.x4.
// A ~ (Ah+Al), W ~ (Wh+Wl); acc = Ah*Wh + Ah*Wl + Al*Wh in fp32.
// ---------------------------------------------------------------------------
constexpr int ROW_B   = 80;                 // smem bytes per 32-bf16 row (64B data + 16B pad)
constexpr int TILE_B  = 128 * ROW_B;        // 10240 B per operand tile
constexpr int STAGE_B = 4 * TILE_B;         // 40960 B per stage
constexpr int GEMM_SMEM = 2 * STAGE_B;      // 81920 B
constexpr int NCH = Cc / 32;                // 32 K-chunks

__device__ __forceinline__ void load_chunk(
    uint32_t sbase, const __nv_bfloat16* const* tiles, int tid, int c)
{
#pragma unroll
    for (int tt = 0; tt < 4; tt++) {
#pragma unroll
        for (int jj = 0; jj < 2; jj++) {
            const int l = tid + jj * 256;          // 0..511
            const int r = l >> 2;                  // row 0..127
            const int u = l & 3;                   // 16B unit 0..3
            const __nv_bfloat16* src = tiles[tt] + (size_t)r * Cc + c * 32 + u * 8;
            const uint32_t dst = sbase + tt * TILE_B + r * ROW_B + u * 16;
            CP_ASYNC16(dst, src);
        }
    }
}

template<bool SPLIT>
__device__ __forceinline__ void gemm_mma_body(
    const __nv_bfloat16* __restrict__ Ah, const __nv_bfloat16* __restrict__ Al,
    const __nv_bfloat16* __restrict__ Wh, const __nv_bfloat16* __restrict__ Wl,
    const float* __restrict__ bias, float* __restrict__ out)
{
    extern __shared__ char smem[];
    const uint32_t sb = smem_u32_of(smem);
    const int tid = threadIdx.x;
    const int wid = tid >> 5;
    const int lane = tid & 31;
    const int m0 = blockIdx.y * 128;
    const int n0 = blockIdx.x * 128;
    const int warp_m = wid >> 2;     // 0..1
    const int warp_n = wid & 3;      // 0..3

    const __nv_bfloat16* tiles[4] = {
        Ah + (size_t)m0 * Cc, Al + (size_t)m0 * Cc,
        Wh + (size_t)n0 * Cc, Wl + (size_t)n0 * Cc
    };

    // per-lane ldmatrix base offsets
    const int sub = lane >> 3;   // matrix index 0..3
    const int r8  = lane & 7;    // row within 8x8
    uint32_t aoff[4], boff[2];
#pragma unroll
    for (int mf = 0; mf < 4; mf++)
        aoff[mf] = (uint32_t)((warp_m * 64 + mf * 16 + (sub & 1) * 8 + r8) * ROW_B
                              + (sub >> 1) * 16);
#pragma unroll
    for (int p = 0; p < 2; p++)
        boff[p] = (uint32_t)((warp_n * 32 + (2 * p + (sub >> 1)) * 8 + r8) * ROW_B
                             + (sub & 1) * 16);

    float acc[4][4][4];
#pragma unroll
    for (int i = 0; i < 4; i++)
#pragma unroll
        for (int j = 0; j < 4; j++)
#pragma unroll
            for (int q = 0; q < 4; q++) acc[i][j][q] = 0.f;

    load_chunk(sb, tiles, tid, 0);
    CP_COMMIT();

#pragma unroll 1
    for (int c = 0; c < NCH; c++) {
        if (c + 1 < NCH) {
            load_chunk(sb + ((c + 1) & 1) * STAGE_B, tiles, tid, c + 1);
            CP_COMMIT();
            CP_WAIT(1);
        } else {
            CP_WAIT(0);
        }
        __syncthreads();
        const uint32_t st = sb + (c & 1) * STAGE_B;

#pragma unroll
        for (int s = 0; s < 2; s++) {         // two k16 steps per chunk
            const uint32_t ko = s * 32;       // 16 bf16 = 32B
            uint32_t ah[4][4], al[4][4], bh[2][4], bl[2][4];
#pragma unroll
            for (int mf = 0; mf < 4; mf++) LDM4(ah[mf], st + aoff[mf] + ko);
#pragma unroll
            for (int mf = 0; mf < 4; mf++) LDM4(al[mf], st + TILE_B + aoff[mf] + ko);
#pragma unroll
            for (int p = 0; p < 2; p++)    LDM4(bh[p], st + 2 * TILE_B + boff[p] + ko);
#pragma unroll
            for (int p = 0; p < 2; p++)    LDM4(bl[p], st + 3 * TILE_B + boff[p] + ko);

#pragma unroll
            for (int mf = 0; mf < 4; mf++) {
#pragma unroll
                for (int fn = 0; fn < 4; fn++) {
                    const int p = fn >> 1, q = fn & 1;
                    MMA_BF16(acc[mf][fn], ah[mf], bh[p][q * 2], bh[p][q * 2 + 1]);
                    MMA_BF16(acc[mf][fn], ah[mf], bl[p][q * 2], bl[p][q * 2 + 1]);
                    MMA_BF16(acc[mf][fn], al[mf], bh[p][q * 2], bh[p][q * 2 + 1]);
                }
            }
        }
        __syncthreads();
    }

    // epilogue: c0,c1 at (m=g, n=2t4), c2,c3 at (m=g+8, n=2t4)
    const int g = lane >> 2, t4 = lane & 3;
#pragma unroll
    for (int mf = 0; mf < 4; mf++) {
#pragma unroll
        for (int fn = 0; fn < 4; fn++) {
            const int m = m0 + warp_m * 64 + mf * 16 + g;
            const int n = n0 + warp_n * 32 + fn * 8 + t4 * 2;
            const float bx = bias[n], by = bias[n + 1];
            float2 v0 = make_float2(acc[mf][fn][0] + bx, acc[mf][fn][1] + by);
            float2 v1 = make_float2(acc[mf][fn][2] + bx, acc[mf][fn][3] + by);
            if (SPLIT) {
                const int h = n >> 6, d = n & 63;
                const int bb0 = m >> 11, t0 = m & (Tc - 1);
                const int bb1 = (m + 8) >> 11, t1 = (m + 8) & (Tc - 1);
                *(float2*)(out + ((size_t)(bb0 * Hc + h) * Tc + t0) * Dc + d) = v0;
                *(float2*)(out + ((size_t)(bb1 * Hc + h) * Tc + t1) * Dc + d) = v1;
            } else {
                *(float2*)(out + (size_t)m * Cc + n) = v0;
                *(float2*)(out + (size_t)(m + 8) * Cc + n) = v1;
            }
        }
    }
}

__global__ __launch_bounds__(256, 1) void qkv_mm_kernel(
    const float* __restrict__ bq, const float* __restrict__ bk, const float* __restrict__ bv)
{
    const __nv_bfloat16 *Wh, *Wl;
    const float* bias;
    float* out;
    switch (blockIdx.z) {
        case 0:  Wh = g_wqh; Wl = g_wql; bias = bq; out = g_q; break;
        case 1:  Wh = g_wkh; Wl = g_wkl; bias = bk; out = g_k; break;
        default: Wh = g_wvh; Wl = g_wvl; bias = bv; out = g_v; break;
    }
    gemm_mma_body<true>(g_xh, g_xl, Wh, Wl, bias, out);
}

__global__ __launch_bounds__(256, 1) void proj_mm_kernel(
    const float* __restrict__ bp, float* __restrict__ out)
{
    gemm_mma_body<false>(g_ah, g_al, g_wph, g_wpl, bp, out);
}

// ---------------------------------------------------------------------------
// Causal flash attention, fp32 SIMT (unchanged — next round's target).
// ---------------------------------------------------------------------------
__global__ __launch_bounds__(64) void flash_kernel()
{
    __shared__ float Ks[64][64];
    __shared__ float Vs[64][64];
    const int tid = threadIdx.x;
    const int qt = blockIdx.x, h = blockIdx.y, b = blockIdx.z;
    const size_t head_off = (size_t)(b * Hc + h) * Tc * Dc;
    const float* qb = g_q + head_off;
    const float* kb = g_k + head_off;
    const float* vb = g_v + head_off;
    const int qglob = qt * 64 + tid;
    const float NEG_INF = __int_as_float(0xff800000);

    float qr[64];
    {
        const float4* qsrc = (const float4*)(qb + (size_t)qglob * Dc);
#pragma unroll
        for (int k4 = 0; k4 < 16; k4++) {
            float4 t4 = qsrc[k4];
            qr[k4 * 4 + 0] = t4.x * 0.125f;
            qr[k4 * 4 + 1] = t4.y * 0.125f;
            qr[k4 * 4 + 2] = t4.z * 0.125f;
            qr[k4 * 4 + 3] = t4.w * 0.125f;
        }
    }

    float o[64];
#pragma unroll
    for (int d = 0; d < 64; d++) o[d] = 0.f;
    float mi = NEG_INF, li = 0.f;

#pragma unroll 1
    for (int kt = 0; kt <= qt; kt++) {
        __syncthreads();
        {
            const float4* ksrc = (const float4*)(kb + (size_t)kt * 64 * Dc);
            const float4* vsrc = (const float4*)(vb + (size_t)kt * 64 * Dc);
            float4* kd = (float4*)&Ks[0][0];
            float4* vd = (float4*)&Vs[0][0];
            for (int idx = tid; idx < 1024; idx += 64) {
                kd[idx] = ksrc[idx];
                vd[idx] = vsrc[idx];
            }
        }
        __syncthreads();
        const bool diag = (kt == qt);

#pragma unroll 1
        for (int j0 = 0; j0 < 64; j0 += 8) {
            if (diag && j0 > tid) break;

            float s[8];
#pragma unroll
            for (int jj = 0; jj < 8; jj++) {
                const float4* krow = (const float4*)&Ks[j0 + jj][0];
                float a0 = 0.f, a1 = 0.f, a2 = 0.f, a3 = 0.f;
#pragma unroll
                for (int k4 = 0; k4 < 16; k4++) {
                    float4 kv = krow[k4];
                    a0 = fmaf(qr[k4 * 4 + 0], kv.x, a0);
                    a1 = fmaf(qr[k4 * 4 + 1], kv.y, a1);
                    a2 = fmaf(qr[k4 * 4 + 2], kv.z, a2);
                    a3 = fmaf(qr[k4 * 4 + 3], kv.w, a3);
                }
                float sv = (a0 + a1) + (a2 + a3);
                if (diag && (j0 + jj > tid)) sv = NEG_INF;
                s[jj] = sv;
            }

            float mc = s[0];
#pragma unroll
            for (int jj = 1; jj < 8; jj++) mc = fmaxf(mc, s[jj]);
            const float mnew = fmaxf(mi, mc);
            const float corr = __expf(mi - mnew);
            li *= corr;
#pragma unroll
            for (int d = 0; d < 64; d++) o[d] *= corr;

            float p[8];
#pragma unroll
            for (int jj = 0; jj < 8; jj++) {
                p[jj] = __expf(s[jj] - mnew);
                li += p[jj];
            }
            mi = mnew;

#pragma unroll
            for (int jj = 0; jj < 8; jj++) {
                const float4* vrow = (const float4*)&Vs[j0 + jj][0];
#pragma unroll
                for (int k4 = 0; k4 < 16; k4++) {
                    float4 vv = vrow[k4];
                    o[k4 * 4 + 0] = fmaf(p[jj], vv.x, o[k4 * 4 + 0]);
                    o[k4 * 4 + 1] = fmaf(p[jj], vv.y, o[k4 * 4 + 1]);
                    o[k4 * 4 + 2] = fmaf(p[jj], vv.z, o[k4 * 4 + 2]);
                    o[k4 * 4 + 3] = fmaf(p[jj], vv.w, o[k4 * 4 + 3]);
                }
            }
        }
    }

    const float inv = 1.f / li;
    float* yrow = g_att + ((size_t)b * Tc + qglob) * Cc + h * Dc;
#pragma unroll
    for (int k4 = 0; k4 < 16; k4++) {
        float4 w4;
        w4.x = o[k4 * 4 + 0] * inv;
        w4.y = o[k4 * 4 + 1] * inv;
        w4.z = o[k4 * 4 + 2] * inv;
        w4.w = o[k4 * 4 + 3] * inv;
        ((float4*)yrow)[k4] = w4;
    }
}

// ---------------------------------------------------------------------------
// Input order (setup_inputs): x, Wk, bk, Wq, bq, Wv, bv, Wp, bp
// ---------------------------------------------------------------------------
extern "C" void kernel_launch(void* const* d_in, const int* in_sizes, int n_in,
                              void* d_out, int out_size)
{
    const float* x  = (const float*)d_in[0];
    const float* Wk = (const float*)d_in[1];
    const float* bk = (const float*)d_in[2];
    const float* Wq = (const float*)d_in[3];
    const float* bq = (const float*)d_in[4];
    const float* Wv = (const float*)d_in[5];
    const float* bv = (const float*)d_in[6];
    const float* Wp = (const float*)d_in[7];
    const float* bp = (const float*)d_in[8];
    float* out = (float*)d_out;

    cudaFuncSetAttribute(qkv_mm_kernel, cudaFuncAttributeMaxDynamicSharedMemorySize, GEMM_SMEM);
    cudaFuncSetAttribute(proj_mm_kernel, cudaFuncAttributeMaxDynamicSharedMemorySize, GEMM_SMEM);

    __nv_bfloat16 *xh, *xl, *ah, *al, *wqh, *wql, *wkh, *wkl, *wvh, *wvl, *wph, *wpl;
    cudaGetSymbolAddress((void**)&xh,  g_xh);  cudaGetSymbolAddress((void**)&xl,  g_xl);
    cudaGetSymbolAddress((void**)&ah,  g_ah);  cudaGetSymbolAddress((void**)&al,  g_al);
    cudaGetSymbolAddress((void**)&wqh, g_wqh); cudaGetSymbolAddress((void**)&wql, g_wql);
    cudaGetSymbolAddress((void**)&wkh, g_wkh); cudaGetSymbolAddress((void**)&wkl, g_wkl);
    cudaGetSymbolAddress((void**)&wvh, g_wvh); cudaGetSymbolAddress((void**)&wvl, g_wvl);
    cudaGetSymbolAddress((void**)&wph, g_wph); cudaGetSymbolAddress((void**)&wpl, g_wpl);
    float* gatt; cudaGetSymbolAddress((void**)&gatt, g_att);

    // fp32 -> bf16 hi/lo splits
    convert_kernel<<<(Mc * Cc / 4) / 256, 256>>>(x,  xh,  xl,  Mc * Cc / 4);
    convert_kernel<<<(Cc * Cc / 4) / 256, 256>>>(Wq, wqh, wql, Cc * Cc / 4);
    convert_kernel<<<(Cc * Cc / 4) / 256, 256>>>(Wk, wkh, wkl, Cc * Cc / 4);
    convert_kernel<<<(Cc * Cc / 4) / 256, 256>>>(Wv, wvh, wvl, Cc * Cc / 4);
    convert_kernel<<<(Cc * Cc / 4) / 256, 256>>>(Wp, wph, wpl, Cc * Cc / 4);

    // QKV projections on warp-MMA tensor path
    qkv_mm_kernel<<<dim3(Cc / 128, Mc / 128, 3), 256, GEMM_SMEM>>>(bq, bk, bv);

    // attention
    flash_kernel<<<dim3(Tc / 64, Hc, Bc), 64>>>();

    // split attention output, output projection
    convert_kernel<<<(Mc * Cc / 4) / 256, 256>>>(gatt, ah, al, Mc * Cc / 4);
    proj_mm_kernel<<<dim3(Cc / 128, Mc / 128, 1), 256, GEMM_SMEM>>>(bp, out);
}